// round 9
// baseline (speedup 1.0000x reference)
#include <cuda_runtime.h>
#include <cuda_fp16.h>
#include <cstdint>

#define D 128
#define NG 64
#define CO 16
#define MAXN 50176
#define MAXE 600064
#define NEG 0.1f
#define AST 132   // padded smem row stride (floats)

// -------- scratch (device globals: allocation-free workaround) --------
__device__ float  g_h1[MAXN * D];
__device__ float  g_h2[MAXN * D];
__device__ __half g_hh[MAXN * D];     // fp16 copy of GEMM output for gathers
__device__ float  g_BH1[D * D];
__device__ float  g_BL1[D * D];
__device__ float  g_BH2[D * D];
__device__ float  g_BL2[D * D];
__device__ float  g_dinv[MAXN];
__device__ int    g_degi[MAXN];
__device__ int    g_rowptr[MAXN + 1];
__device__ int    g_fill[MAXN];
__device__ int    g_csr_src[MAXE];
__device__ float  g_csr_coef[MAXE];   // dinv[src]*dinv[dst] per CSR slot
__device__ int    g_bpub[64];
__device__ float  g_pool[NG * D];
__device__ float  g_cnt[NG];

__device__ __forceinline__ float lrelu(float v) {
    return v >= 0.0f ? v : NEG * v;
}
__device__ __forceinline__ uint32_t tf32bits(float x) {
    uint32_t u;
    asm("cvt.rna.tf32.f32 %0, %1;" : "=r"(u) : "f"(x));
    return u;
}
__device__ __forceinline__ void mma8(float* c, const uint32_t* a, uint32_t b0, uint32_t b1) {
    asm volatile(
        "mma.sync.aligned.m16n8k8.row.col.f32.tf32.tf32.f32 "
        "{%0,%1,%2,%3}, {%4,%5,%6,%7}, {%8,%9}, {%0,%1,%2,%3};"
        : "+f"(c[0]), "+f"(c[1]), "+f"(c[2]), "+f"(c[3])
        : "r"(a[0]), "r"(a[1]), "r"(a[2]), "r"(a[3]), "r"(b0), "r"(b1));
}

// -------- init: zero degi/pool/cnt/bpub + tf32-split both W's (transposed) -----
__global__ void k_init(const float* __restrict__ W1, const float* __restrict__ W2, int n) {
    int stride = gridDim.x * blockDim.x;
    int i0 = blockIdx.x * blockDim.x + threadIdx.x;
    for (int i = i0; i < n; i += stride) g_degi[i] = 0;
    for (int i = i0; i < NG * D; i += stride) g_pool[i] = 0.0f;
    for (int i = i0; i < NG; i += stride) g_cnt[i] = 0.0f;
    for (int i = i0; i < 64; i += stride) g_bpub[i] = 0;
    for (int i = i0; i < D * D; i += stride) {
        int nn = i >> 7, k = i & 127;
        float w1 = W1[k * D + nn];
        float h1 = __uint_as_float(tf32bits(w1));
        g_BH1[i] = h1;
        g_BL1[i] = __uint_as_float(tf32bits(w1 - h1));
        float w2 = W2[k * D + nn];
        float h2 = __uint_as_float(tf32bits(w2));
        g_BH2[i] = h2;
        g_BL2[i] = __uint_as_float(tf32bits(w2 - h2));
    }
}

// -------- histogram over dst + graph node counts (fused) --------
__global__ void k_hist(const int* __restrict__ dst, const int* __restrict__ batch,
                       int E, int n) {
    int stride = gridDim.x * blockDim.x;
    int i0 = blockIdx.x * blockDim.x + threadIdx.x;
    for (int e = i0; e < E; e += stride)
        atomicAdd(&g_degi[dst[e]], 1);
    for (int i = i0; i < n; i += stride)
        atomicAdd(&g_cnt[batch[i]], 1.0f);
}

// -------- single-kernel scan: decoupled lookback --------
__global__ void k_scan(int n, int nblk) {
    __shared__ int sm[1024];
    __shared__ int s_off;
    int t = threadIdx.x, b = blockIdx.x;
    int i = b * 1024 + t;
    int d = (i < n) ? g_degi[i] : 0;
    sm[t] = d;
    __syncthreads();
    #pragma unroll
    for (int off = 1; off < 1024; off <<= 1) {
        int u = (t >= off) ? sm[t - off] : 0;
        __syncthreads();
        sm[t] += u;
        __syncthreads();
    }
    if (t == 0) atomicExch(&g_bpub[b], sm[1023] + 1);
    if (t < 32) {
        int acc = 0;
        for (int j = t; j < b; j += 32) {
            int v;
            do { v = atomicAdd(&g_bpub[j], 0); } while (v == 0);
            acc += v - 1;
        }
        #pragma unroll
        for (int off = 16; off; off >>= 1) acc += __shfl_down_sync(~0u, acc, off);
        if (t == 0) s_off = acc;
    }
    __syncthreads();
    int off = s_off;
    if (i < n) {
        int excl = off + sm[t] - d;
        g_rowptr[i] = excl;
        g_fill[i] = excl;
        g_dinv[i] = rsqrtf((float)d + 1.0f);
    }
    if (b == nblk - 1 && t == 1023) g_rowptr[n] = off + sm[1023];
}

// -------- permute edges into CSR + precompute per-edge coef --------
__global__ void k_permute(const int* __restrict__ src, const int* __restrict__ dst, int E) {
    int stride = gridDim.x * blockDim.x;
    for (int e = blockIdx.x * blockDim.x + threadIdx.x; e < E; e += stride) {
        int d = dst[e];
        int s = src[e];
        int pos = atomicAdd(&g_fill[d], 1);
        g_csr_src[pos] = s;
        g_csr_coef[pos] = g_dinv[s] * g_dinv[d];
    }
}

// ===================== tf32x3 HMMA GEMM (4m x 2n warp grid) =====================
__global__ void __launch_bounds__(256, 1)
k_gemm_mma(const float* __restrict__ A, const float* __restrict__ BhiG,
           const float* __restrict__ BloG, float* __restrict__ out,
           __half* __restrict__ outh, int n) {
    extern __shared__ float sm[];
    float* As = sm;
    float* Bh = sm + 128 * AST;
    float* Bl = Bh + 128 * AST;

    int t = threadIdx.x;
    int r0 = blockIdx.x * 128;
    int rows = n - r0;
    if (rows > 128) rows = 128;

    const float4* A4 = (const float4*)(A + (size_t)r0 * D);
    for (int i = t; i < 128 * 32; i += 256) {
        int row = i >> 5, c4 = i & 31;
        float4 v = (row < rows) ? A4[row * 32 + c4] : make_float4(0.f, 0.f, 0.f, 0.f);
        *(float4*)&As[row * AST + c4 * 4] = v;
        *(float4*)&Bh[row * AST + c4 * 4] = ((const float4*)BhiG)[i];
        *(float4*)&Bl[row * AST + c4 * 4] = ((const float4*)BloG)[i];
    }
    __syncthreads();

    int wid = t >> 5, lane = t & 31;
    int gid = lane >> 2, tig = lane & 3;
    int wm = wid >> 1, wn = wid & 1;

    float acc[2][8][4];
    #pragma unroll
    for (int s = 0; s < 2; s++)
        #pragma unroll
        for (int nt = 0; nt < 8; nt++)
            #pragma unroll
            for (int q = 0; q < 4; q++) acc[s][nt][q] = 0.0f;

    const float* a00 = &As[(wm * 32 + gid) * AST];
    const float* a01 = &As[(wm * 32 + gid + 8) * AST];
    const float* a10 = &As[(wm * 32 + 16 + gid) * AST];
    const float* a11 = &As[(wm * 32 + 24 + gid) * AST];

    #pragma unroll 2
    for (int k8 = 0; k8 < D; k8 += 8) {
        float v0 = a00[k8 + tig], v1 = a01[k8 + tig];
        float v2 = a00[k8 + tig + 4], v3 = a01[k8 + tig + 4];
        float u0 = a10[k8 + tig], u1 = a11[k8 + tig];
        float u2 = a10[k8 + tig + 4], u3 = a11[k8 + tig + 4];
        uint32_t ah0[4], al0[4], ah1[4], al1[4];
        ah0[0] = tf32bits(v0); al0[0] = tf32bits(v0 - __uint_as_float(ah0[0]));
        ah0[1] = tf32bits(v1); al0[1] = tf32bits(v1 - __uint_as_float(ah0[1]));
        ah0[2] = tf32bits(v2); al0[2] = tf32bits(v2 - __uint_as_float(ah0[2]));
        ah0[3] = tf32bits(v3); al0[3] = tf32bits(v3 - __uint_as_float(ah0[3]));
        ah1[0] = tf32bits(u0); al1[0] = tf32bits(u0 - __uint_as_float(ah1[0]));
        ah1[1] = tf32bits(u1); al1[1] = tf32bits(u1 - __uint_as_float(ah1[1]));
        ah1[2] = tf32bits(u2); al1[2] = tf32bits(u2 - __uint_as_float(ah1[2]));
        ah1[3] = tf32bits(u3); al1[3] = tf32bits(u3 - __uint_as_float(ah1[3]));

        #pragma unroll
        for (int nt = 0; nt < 8; nt++) {
            int brow = (wn * 64 + nt * 8 + gid) * AST + k8;
            uint32_t bh0 = __float_as_uint(Bh[brow + tig]);
            uint32_t bh1 = __float_as_uint(Bh[brow + tig + 4]);
            uint32_t bl0 = __float_as_uint(Bl[brow + tig]);
            uint32_t bl1 = __float_as_uint(Bl[brow + tig + 4]);
            mma8(acc[0][nt], ah0, bh0, bh1);
            mma8(acc[0][nt], al0, bh0, bh1);
            mma8(acc[0][nt], ah0, bl0, bl1);
            mma8(acc[1][nt], ah1, bh0, bh1);
            mma8(acc[1][nt], al1, bh0, bh1);
            mma8(acc[1][nt], ah1, bl0, bl1);
        }
    }

    #pragma unroll
    for (int s = 0; s < 2; s++) {
        int m0 = wm * 32 + s * 16 + gid;
        int m1 = m0 + 8;
        float*  o0 = out  + (size_t)(r0 + m0) * D + wn * 64;
        float*  o1 = out  + (size_t)(r0 + m1) * D + wn * 64;
        __half* p0 = outh + (size_t)(r0 + m0) * D + wn * 64;
        __half* p1 = outh + (size_t)(r0 + m1) * D + wn * 64;
        #pragma unroll
        for (int nt = 0; nt < 8; nt++) {
            int c = nt * 8 + tig * 2;
            if (m0 < rows) {
                *(float2*)&o0[c] = make_float2(acc[s][nt][0], acc[s][nt][1]);
                *(__half2*)&p0[c] = __floats2half2_rn(acc[s][nt][0], acc[s][nt][1]);
            }
            if (m1 < rows) {
                *(float2*)&o1[c] = make_float2(acc[s][nt][2], acc[s][nt][3]);
                *(__half2*)&p1[c] = __floats2half2_rn(acc[s][nt][2], acc[s][nt][3]);
            }
        }
    }
}

// ===================== gather: lane-parallel edge fetch + MLP-4 rows ============
__device__ __forceinline__ void acc_row(float4& acc, const __half* __restrict__ hh,
                                        int s, float c, int lane) {
    uint2 q = ((const uint2*)(hh + (size_t)s * D))[lane];
    float2 a0 = __half22float2(*(__half2*)&q.x);
    float2 a1 = __half22float2(*(__half2*)&q.y);
    acc.x += c * a0.x; acc.y += c * a0.y;
    acc.z += c * a1.x; acc.w += c * a1.y;
}

__device__ __forceinline__ void gcn_body(const float* __restrict__ h,
                                         const __half* __restrict__ hh,
                                         const float* __restrict__ bias,
                                         int node, int lane, float4& r) {
    int beg = g_rowptr[node], end = g_rowptr[node + 1];
    float di = g_dinv[node];
    float4 acc = make_float4(0.f, 0.f, 0.f, 0.f);

    for (int base = beg; base < end; base += 32) {
        int cnt = end - base;
        if (cnt > 32) cnt = 32;
        int sl = 0; float cl = 0.f;
        if (lane < cnt) {
            sl = g_csr_src[base + lane];      // coalesced
            cl = g_csr_coef[base + lane];     // coalesced
        }
        int j = 0;
        for (; j + 4 <= cnt; j += 4) {
            int s0 = __shfl_sync(~0u, sl, j);
            int s1 = __shfl_sync(~0u, sl, j + 1);
            int s2 = __shfl_sync(~0u, sl, j + 2);
            int s3 = __shfl_sync(~0u, sl, j + 3);
            float c0 = __shfl_sync(~0u, cl, j);
            float c1 = __shfl_sync(~0u, cl, j + 1);
            float c2 = __shfl_sync(~0u, cl, j + 2);
            float c3 = __shfl_sync(~0u, cl, j + 3);
            // 4 independent row loads -> MLP 4
            uint2 q0 = ((const uint2*)(hh + (size_t)s0 * D))[lane];
            uint2 q1 = ((const uint2*)(hh + (size_t)s1 * D))[lane];
            uint2 q2 = ((const uint2*)(hh + (size_t)s2 * D))[lane];
            uint2 q3 = ((const uint2*)(hh + (size_t)s3 * D))[lane];
            float2 x0 = __half22float2(*(__half2*)&q0.x), y0 = __half22float2(*(__half2*)&q0.y);
            float2 x1 = __half22float2(*(__half2*)&q1.x), y1 = __half22float2(*(__half2*)&q1.y);
            float2 x2 = __half22float2(*(__half2*)&q2.x), y2 = __half22float2(*(__half2*)&q2.y);
            float2 x3 = __half22float2(*(__half2*)&q3.x), y3 = __half22float2(*(__half2*)&q3.y);
            acc.x += c0 * x0.x + c1 * x1.x + c2 * x2.x + c3 * x3.x;
            acc.y += c0 * x0.y + c1 * x1.y + c2 * x2.y + c3 * x3.y;
            acc.z += c0 * y0.x + c1 * y1.x + c2 * y2.x + c3 * y3.x;
            acc.w += c0 * y0.y + c1 * y1.y + c2 * y2.y + c3 * y3.y;
        }
        for (; j < cnt; j++) {
            int s0 = __shfl_sync(~0u, sl, j);
            float c0 = __shfl_sync(~0u, cl, j);
            acc_row(acc, hh, s0, c0, lane);
        }
    }

    float4 hv = ((const float4*)(h + (size_t)node * D))[lane];
    float4 b = ((const float4*)bias)[lane];
    float d2 = di * di;
    r.x = lrelu(acc.x + hv.x * d2 + b.x);
    r.y = lrelu(acc.y + hv.y * d2 + b.y);
    r.z = lrelu(acc.z + hv.z * d2 + b.z);
    r.w = lrelu(acc.w + hv.w * d2 + b.w);
}

__global__ void k_gcn(const float* __restrict__ h, const __half* __restrict__ hh,
                      const float* __restrict__ bias, float* __restrict__ out, int n) {
    int node = blockIdx.x * 8 + (threadIdx.x >> 5);
    if (node >= n) return;
    int lane = threadIdx.x & 31;
    float4 r;
    gcn_body(h, hh, bias, node, lane, r);
    ((float4*)(out + (size_t)node * D))[lane] = r;
}

__global__ void k_gcn_pool(const float* __restrict__ h, const __half* __restrict__ hh,
                           const float* __restrict__ bias,
                           const int* __restrict__ batch, int n) {
    int node = blockIdx.x * 8 + (threadIdx.x >> 5);
    if (node >= n) return;
    int lane = threadIdx.x & 31;
    float4 r;
    gcn_body(h, hh, bias, node, lane, r);
    int gid = batch[node];
    atomicAdd(((float4*)g_pool) + gid * 32 + lane, r);
}

__global__ void k_final(const float* __restrict__ Wl, const float* __restrict__ bl,
                        float* __restrict__ out) {
    int t = threadIdx.x;
    int g = t >> 4;
    int c = t & 15;
    float cnt = fmaxf(g_cnt[g], 1.0f);
    float s = 0.0f;
    #pragma unroll 8
    for (int f = 0; f < D; f++)
        s += g_pool[g * D + f] * Wl[f * CO + c];
    out[g * CO + c] = s / cnt + bl[c];
}

extern "C" void kernel_launch(void* const* d_in, const int* in_sizes, int n_in,
                              void* d_out, int out_size) {
    const float* x     = (const float*)d_in[0];
    const int*   ei    = (const int*)d_in[1];
    const int*   batch = (const int*)d_in[2];
    const float* W1    = (const float*)d_in[3];
    const float* b1    = (const float*)d_in[4];
    const float* W2    = (const float*)d_in[5];
    const float* b2    = (const float*)d_in[6];
    const float* Wl    = (const float*)d_in[7];
    const float* bl    = (const float*)d_in[8];

    int n = in_sizes[0] / D;
    int E = in_sizes[1] / 2;
    const int* src = ei;
    const int* dst = ei + E;

    void *ph1, *ph2, *phh, *pbh1, *pbl1, *pbh2, *pbl2;
    cudaGetSymbolAddress(&ph1, g_h1);
    cudaGetSymbolAddress(&ph2, g_h2);
    cudaGetSymbolAddress(&phh, g_hh);
    cudaGetSymbolAddress(&pbh1, g_BH1);
    cudaGetSymbolAddress(&pbl1, g_BL1);
    cudaGetSymbolAddress(&pbh2, g_BH2);
    cudaGetSymbolAddress(&pbl2, g_BL2);
    float* h1 = (float*)ph1;
    float* h2 = (float*)ph2;
    __half* hh = (__half*)phh;

    int smem = 3 * 128 * AST * (int)sizeof(float);   // 202752 B
    cudaFuncSetAttribute(k_gemm_mma, cudaFuncAttributeMaxDynamicSharedMemorySize, smem);

    int nblk = (n + 1023) / 1024;
    int nblocks8 = (n + 7) / 8;
    int gtiles = (n + 127) / 128;

    // CSR build
    k_init<<<512, 256>>>(W1, W2, n);
    k_hist<<<1024, 256>>>(dst, batch, E, n);
    k_scan<<<nblk, 1024>>>(n, nblk);
    k_permute<<<1024, 256>>>(src, dst, E);

    // Layer 1
    k_gemm_mma<<<gtiles, 256, smem>>>(x, (float*)pbh1, (float*)pbl1, h1, hh, n);
    k_gcn<<<nblocks8, 256>>>(h1, hh, b1, h2, n);

    // Layer 2
    k_gemm_mma<<<gtiles, 256, smem>>>(h2, (float*)pbh2, (float*)pbl2, h1, hh, n);
    k_gcn_pool<<<nblocks8, 256>>>(h1, hh, b2, batch, n);

    // Head
    k_final<<<1, 1024>>>(Wl, bl, (float*)d_out);
}

// round 10
// speedup vs baseline: 1.2306x; 1.2306x over previous
#include <cuda_runtime.h>
#include <cuda_fp16.h>
#include <cstdint>

#define D 128
#define NG 64
#define CO 16
#define MAXN 50176
#define MAXE 600064
#define NEG 0.1f
#define AST 132   // padded smem row stride (floats)

// -------- scratch (device globals: allocation-free workaround) --------
__device__ float  g_h1[MAXN * D];
__device__ float  g_h2[MAXN * D];
__device__ __half g_hh[MAXN * D];     // fp16 copy of GEMM output for gathers
__device__ float  g_BH1[D * D];       // W1^T, tf32-rounded
__device__ float  g_BH2[D * D];       // W2^T, tf32-rounded
__device__ float  g_dinv[MAXN];
__device__ int    g_degi[MAXN];
__device__ int    g_rowptr[MAXN + 1];
__device__ int    g_fill[MAXN];
__device__ int    g_csr_src[MAXE];
__device__ int    g_bpub[64];
__device__ float  g_pool[NG * D];
__device__ float  g_cnt[NG];

__device__ __forceinline__ float lrelu(float v) {
    return v >= 0.0f ? v : NEG * v;
}
__device__ __forceinline__ uint32_t tf32bits(float x) {
    uint32_t u;
    asm("cvt.rna.tf32.f32 %0, %1;" : "=r"(u) : "f"(x));
    return u;
}
__device__ __forceinline__ void mma8(float* c, const uint32_t* a, uint32_t b0, uint32_t b1) {
    asm volatile(
        "mma.sync.aligned.m16n8k8.row.col.f32.tf32.tf32.f32 "
        "{%0,%1,%2,%3}, {%4,%5,%6,%7}, {%8,%9}, {%0,%1,%2,%3};"
        : "+f"(c[0]), "+f"(c[1]), "+f"(c[2]), "+f"(c[3])
        : "r"(a[0]), "r"(a[1]), "r"(a[2]), "r"(a[3]), "r"(b0), "r"(b1));
}

// -------- init: zero degi/pool/cnt/bpub + tf32-round both W's (transposed) -----
__global__ void k_init(const float* __restrict__ W1, const float* __restrict__ W2, int n) {
    int stride = gridDim.x * blockDim.x;
    int i0 = blockIdx.x * blockDim.x + threadIdx.x;
    for (int i = i0; i < n; i += stride) g_degi[i] = 0;
    for (int i = i0; i < NG * D; i += stride) g_pool[i] = 0.0f;
    for (int i = i0; i < NG; i += stride) g_cnt[i] = 0.0f;
    for (int i = i0; i < 64; i += stride) g_bpub[i] = 0;
    for (int i = i0; i < D * D; i += stride) {
        int nn = i >> 7, k = i & 127;
        g_BH1[i] = __uint_as_float(tf32bits(W1[k * D + nn]));
        g_BH2[i] = __uint_as_float(tf32bits(W2[k * D + nn]));
    }
}

// -------- histogram over dst + graph node counts (fused) --------
__global__ void k_hist(const int* __restrict__ dst, const int* __restrict__ batch,
                       int E, int n) {
    int stride = gridDim.x * blockDim.x;
    int i0 = blockIdx.x * blockDim.x + threadIdx.x;
    for (int e = i0; e < E; e += stride)
        atomicAdd(&g_degi[dst[e]], 1);
    for (int i = i0; i < n; i += stride)
        atomicAdd(&g_cnt[batch[i]], 1.0f);
}

// -------- single-kernel scan: decoupled lookback --------
__global__ void k_scan(int n, int nblk) {
    __shared__ int sm[1024];
    __shared__ int s_off;
    int t = threadIdx.x, b = blockIdx.x;
    int i = b * 1024 + t;
    int d = (i < n) ? g_degi[i] : 0;
    sm[t] = d;
    __syncthreads();
    #pragma unroll
    for (int off = 1; off < 1024; off <<= 1) {
        int u = (t >= off) ? sm[t - off] : 0;
        __syncthreads();
        sm[t] += u;
        __syncthreads();
    }
    if (t == 0) atomicExch(&g_bpub[b], sm[1023] + 1);
    if (t < 32) {
        int acc = 0;
        for (int j = t; j < b; j += 32) {
            int v;
            do { v = atomicAdd(&g_bpub[j], 0); } while (v == 0);
            acc += v - 1;
        }
        #pragma unroll
        for (int off = 16; off; off >>= 1) acc += __shfl_down_sync(~0u, acc, off);
        if (t == 0) s_off = acc;
    }
    __syncthreads();
    int off = s_off;
    if (i < n) {
        int excl = off + sm[t] - d;
        g_rowptr[i] = excl;
        g_fill[i] = excl;
        g_dinv[i] = rsqrtf((float)d + 1.0f);
    }
    if (b == nblk - 1 && t == 1023) g_rowptr[n] = off + sm[1023];
}

// -------- permute edges into CSR (by dst) --------
__global__ void k_permute(const int* __restrict__ src, const int* __restrict__ dst, int E) {
    int stride = gridDim.x * blockDim.x;
    for (int e = blockIdx.x * blockDim.x + threadIdx.x; e < E; e += stride) {
        int d = dst[e];
        int pos = atomicAdd(&g_fill[d], 1);
        g_csr_src[pos] = src[e];
    }
}

// ===================== single-pass tf32 HMMA GEMM (4m x 2n warp grid) ===========
// out[n,128] = A[n,128] @ W[128,128]; also writes fp16 copy for the gather.
__global__ void __launch_bounds__(256, 1)
k_gemm_mma(const float* __restrict__ A, const float* __restrict__ BhG,
           float* __restrict__ out, __half* __restrict__ outh, int n) {
    extern __shared__ float sm[];
    float* As = sm;                 // 128 x AST
    float* Bh = sm + 128 * AST;     // 128 x AST  [n][k], tf32-rounded

    int t = threadIdx.x;
    int r0 = blockIdx.x * 128;
    int rows = n - r0;
    if (rows > 128) rows = 128;

    const float4* A4 = (const float4*)(A + (size_t)r0 * D);
    for (int i = t; i < 128 * 32; i += 256) {
        int row = i >> 5, c4 = i & 31;
        float4 v = (row < rows) ? A4[row * 32 + c4] : make_float4(0.f, 0.f, 0.f, 0.f);
        *(float4*)&As[row * AST + c4 * 4] = v;
        *(float4*)&Bh[row * AST + c4 * 4] = ((const float4*)BhG)[i];
    }
    __syncthreads();

    int wid = t >> 5, lane = t & 31;
    int gid = lane >> 2, tig = lane & 3;
    int wm = wid >> 1, wn = wid & 1;

    float acc[2][8][4];
    #pragma unroll
    for (int s = 0; s < 2; s++)
        #pragma unroll
        for (int nt = 0; nt < 8; nt++)
            #pragma unroll
            for (int q = 0; q < 4; q++) acc[s][nt][q] = 0.0f;

    const float* a00 = &As[(wm * 32 + gid) * AST];
    const float* a01 = &As[(wm * 32 + gid + 8) * AST];
    const float* a10 = &As[(wm * 32 + 16 + gid) * AST];
    const float* a11 = &As[(wm * 32 + 24 + gid) * AST];

    #pragma unroll 2
    for (int k8 = 0; k8 < D; k8 += 8) {
        uint32_t ah0[4], ah1[4];
        ah0[0] = tf32bits(a00[k8 + tig]);
        ah0[1] = tf32bits(a01[k8 + tig]);
        ah0[2] = tf32bits(a00[k8 + tig + 4]);
        ah0[3] = tf32bits(a01[k8 + tig + 4]);
        ah1[0] = tf32bits(a10[k8 + tig]);
        ah1[1] = tf32bits(a11[k8 + tig]);
        ah1[2] = tf32bits(a10[k8 + tig + 4]);
        ah1[3] = tf32bits(a11[k8 + tig + 4]);

        #pragma unroll
        for (int nt = 0; nt < 8; nt++) {
            int brow = (wn * 64 + nt * 8 + gid) * AST + k8;
            uint32_t bh0 = __float_as_uint(Bh[brow + tig]);
            uint32_t bh1 = __float_as_uint(Bh[brow + tig + 4]);
            mma8(acc[0][nt], ah0, bh0, bh1);
            mma8(acc[1][nt], ah1, bh0, bh1);
        }
    }

    #pragma unroll
    for (int s = 0; s < 2; s++) {
        int m0 = wm * 32 + s * 16 + gid;
        int m1 = m0 + 8;
        float*  o0 = out  + (size_t)(r0 + m0) * D + wn * 64;
        float*  o1 = out  + (size_t)(r0 + m1) * D + wn * 64;
        __half* p0 = outh + (size_t)(r0 + m0) * D + wn * 64;
        __half* p1 = outh + (size_t)(r0 + m1) * D + wn * 64;
        #pragma unroll
        for (int nt = 0; nt < 8; nt++) {
            int c = nt * 8 + tig * 2;
            if (m0 < rows) {
                *(float2*)&o0[c] = make_float2(acc[s][nt][0], acc[s][nt][1]);
                *(__half2*)&p0[c] = __floats2half2_rn(acc[s][nt][0], acc[s][nt][1]);
            }
            if (m1 < rows) {
                *(float2*)&o1[c] = make_float2(acc[s][nt][2], acc[s][nt][3]);
                *(__half2*)&p1[c] = __floats2half2_rn(acc[s][nt][2], acc[s][nt][3]);
            }
        }
    }
}

// ===================== gather (fp16 neighbors, 2-unrolled) =====================
__device__ __forceinline__ void gcn_body(const float* __restrict__ h,
                                         const __half* __restrict__ hh,
                                         const float* __restrict__ bias,
                                         int node, int lane, float4& r) {
    int beg = g_rowptr[node], end = g_rowptr[node + 1];
    float di = g_dinv[node];
    float4 acc = make_float4(0.f, 0.f, 0.f, 0.f);
    int e = beg;
    for (; e + 2 <= end; e += 2) {
        int s0 = g_csr_src[e], s1 = g_csr_src[e + 1];
        float c0 = g_dinv[s0] * di;
        float c1 = g_dinv[s1] * di;
        uint2 q0 = ((const uint2*)(hh + (size_t)s0 * D))[lane];
        uint2 q1 = ((const uint2*)(hh + (size_t)s1 * D))[lane];
        float2 a0 = __half22float2(*(__half2*)&q0.x);
        float2 a1 = __half22float2(*(__half2*)&q0.y);
        float2 b0 = __half22float2(*(__half2*)&q1.x);
        float2 b1 = __half22float2(*(__half2*)&q1.y);
        acc.x += c0 * a0.x + c1 * b0.x;
        acc.y += c0 * a0.y + c1 * b0.y;
        acc.z += c0 * a1.x + c1 * b1.x;
        acc.w += c0 * a1.y + c1 * b1.y;
    }
    if (e < end) {
        int s0 = g_csr_src[e];
        float c0 = g_dinv[s0] * di;
        uint2 q0 = ((const uint2*)(hh + (size_t)s0 * D))[lane];
        float2 a0 = __half22float2(*(__half2*)&q0.x);
        float2 a1 = __half22float2(*(__half2*)&q0.y);
        acc.x += c0 * a0.x; acc.y += c0 * a0.y;
        acc.z += c0 * a1.x; acc.w += c0 * a1.y;
    }
    float4 hv = ((const float4*)(h + (size_t)node * D))[lane];
    float4 b = ((const float4*)bias)[lane];
    float d2 = di * di;
    r.x = lrelu(acc.x + hv.x * d2 + b.x);
    r.y = lrelu(acc.y + hv.y * d2 + b.y);
    r.z = lrelu(acc.z + hv.z * d2 + b.z);
    r.w = lrelu(acc.w + hv.w * d2 + b.w);
}

__global__ void k_gcn(const float* __restrict__ h, const __half* __restrict__ hh,
                      const float* __restrict__ bias, float* __restrict__ out, int n) {
    int node = blockIdx.x * 8 + (threadIdx.x >> 5);
    if (node >= n) return;
    int lane = threadIdx.x & 31;
    float4 r;
    gcn_body(h, hh, bias, node, lane, r);
    ((float4*)(out + (size_t)node * D))[lane] = r;
}

__global__ void k_gcn_pool(const float* __restrict__ h, const __half* __restrict__ hh,
                           const float* __restrict__ bias,
                           const int* __restrict__ batch, int n) {
    int node = blockIdx.x * 8 + (threadIdx.x >> 5);
    if (node >= n) return;
    int lane = threadIdx.x & 31;
    float4 r;
    gcn_body(h, hh, bias, node, lane, r);
    int gid = batch[node];
    atomicAdd(((float4*)g_pool) + gid * 32 + lane, r);
}

__global__ void k_final(const float* __restrict__ Wl, const float* __restrict__ bl,
                        float* __restrict__ out) {
    int t = threadIdx.x;
    int g = t >> 4;
    int c = t & 15;
    float cnt = fmaxf(g_cnt[g], 1.0f);
    float s = 0.0f;
    #pragma unroll 8
    for (int f = 0; f < D; f++)
        s += g_pool[g * D + f] * Wl[f * CO + c];
    out[g * CO + c] = s / cnt + bl[c];
}

extern "C" void kernel_launch(void* const* d_in, const int* in_sizes, int n_in,
                              void* d_out, int out_size) {
    const float* x     = (const float*)d_in[0];
    const int*   ei    = (const int*)d_in[1];
    const int*   batch = (const int*)d_in[2];
    const float* W1    = (const float*)d_in[3];
    const float* b1    = (const float*)d_in[4];
    const float* W2    = (const float*)d_in[5];
    const float* b2    = (const float*)d_in[6];
    const float* Wl    = (const float*)d_in[7];
    const float* bl    = (const float*)d_in[8];

    int n = in_sizes[0] / D;
    int E = in_sizes[1] / 2;
    const int* src = ei;
    const int* dst = ei + E;

    void *ph1, *ph2, *phh, *pbh1, *pbh2;
    cudaGetSymbolAddress(&ph1, g_h1);
    cudaGetSymbolAddress(&ph2, g_h2);
    cudaGetSymbolAddress(&phh, g_hh);
    cudaGetSymbolAddress(&pbh1, g_BH1);
    cudaGetSymbolAddress(&pbh2, g_BH2);
    float* h1 = (float*)ph1;
    float* h2 = (float*)ph2;
    __half* hh = (__half*)phh;

    int smem = 2 * 128 * AST * (int)sizeof(float);   // 135168 B
    cudaFuncSetAttribute(k_gemm_mma, cudaFuncAttributeMaxDynamicSharedMemorySize, smem);

    int nblk = (n + 1023) / 1024;
    int nblocks8 = (n + 7) / 8;
    int gtiles = (n + 127) / 128;

    // CSR build
    k_init<<<512, 256>>>(W1, W2, n);
    k_hist<<<1024, 256>>>(dst, batch, E, n);
    k_scan<<<nblk, 1024>>>(n, nblk);
    k_permute<<<1024, 256>>>(src, dst, E);

    // Layer 1
    k_gemm_mma<<<gtiles, 256, smem>>>(x, (float*)pbh1, h1, hh, n);
    k_gcn<<<nblocks8, 256>>>(h1, hh, b1, h2, n);

    // Layer 2
    k_gemm_mma<<<gtiles, 256, smem>>>(h2, (float*)pbh2, h1, hh, n);
    k_gcn_pool<<<nblocks8, 256>>>(h1, hh, b2, batch, n);

    // Head
    k_final<<<1, 1024>>>(Wl, bl, (float*)d_out);
}

// round 11
// speedup vs baseline: 1.5932x; 1.2947x over previous
#include <cuda_runtime.h>
#include <cuda_fp16.h>
#include <cstdint>

#define D 128
#define NG 64
#define CO 16
#define MAXN 50176
#define MAXE 600064
#define NEG 0.1f
#define HST 136   // smem row stride in halves: (68*gid + tig) % 32 distinct -> conflict-free

// -------- scratch (device globals: allocation-free workaround) --------
__device__ __half g_ha[MAXN * D];     // GEMM outputs (layer 1 then layer 2)
__device__ __half g_hb[MAXN * D];     // gcn layer-1 output
__device__ __half g_WH1[D * D];       // W1^T fp16
__device__ __half g_WH2[D * D];       // W2^T fp16
__device__ float  g_dinv[MAXN];
__device__ int    g_degi[MAXN];
__device__ int    g_rowptr[MAXN + 1];
__device__ int    g_erank[MAXE];
__device__ int    g_csr_src[MAXE];
__device__ int    g_bpub[64];
__device__ float  g_pool[NG * D];
__device__ float  g_cnt[NG];

__device__ __forceinline__ float lrelu(float v) {
    return v >= 0.0f ? v : NEG * v;
}
__device__ __forceinline__ void mma16(float* c, const uint32_t* a, uint32_t b0, uint32_t b1) {
    asm volatile(
        "mma.sync.aligned.m16n8k16.row.col.f32.f16.f16.f32 "
        "{%0,%1,%2,%3}, {%4,%5,%6,%7}, {%8,%9}, {%0,%1,%2,%3};"
        : "+f"(c[0]), "+f"(c[1]), "+f"(c[2]), "+f"(c[3])
        : "r"(a[0]), "r"(a[1]), "r"(a[2]), "r"(a[3]), "r"(b0), "r"(b1));
}

// -------- init: zero degi/pool/cnt/bpub + fp16 W^T for both layers --------
__global__ void k_init(const float* __restrict__ W1, const float* __restrict__ W2, int n) {
    int stride = gridDim.x * blockDim.x;
    int i0 = blockIdx.x * blockDim.x + threadIdx.x;
    for (int i = i0; i < n; i += stride) g_degi[i] = 0;
    for (int i = i0; i < NG * D; i += stride) g_pool[i] = 0.0f;
    for (int i = i0; i < NG; i += stride) g_cnt[i] = 0.0f;
    for (int i = i0; i < 64; i += stride) g_bpub[i] = 0;
    for (int i = i0; i < D * D; i += stride) {
        int nn = i >> 7, k = i & 127;
        g_WH1[i] = __float2half_rn(W1[k * D + nn]);
        g_WH2[i] = __float2half_rn(W2[k * D + nn]);
    }
}

// -------- histogram over dst (record per-edge rank) + graph node counts --------
__global__ void k_hist(const int* __restrict__ dst, const int* __restrict__ batch,
                       int E, int n) {
    int stride = gridDim.x * blockDim.x;
    int i0 = blockIdx.x * blockDim.x + threadIdx.x;
    for (int e = i0; e < E; e += stride)
        g_erank[e] = atomicAdd(&g_degi[dst[e]], 1);
    for (int i = i0; i < n; i += stride)
        atomicAdd(&g_cnt[batch[i]], 1.0f);
}

// -------- single-kernel scan: decoupled lookback --------
__global__ void k_scan(int n, int nblk) {
    __shared__ int sm[1024];
    __shared__ int s_off;
    int t = threadIdx.x, b = blockIdx.x;
    int i = b * 1024 + t;
    int d = (i < n) ? g_degi[i] : 0;
    sm[t] = d;
    __syncthreads();
    #pragma unroll
    for (int off = 1; off < 1024; off <<= 1) {
        int u = (t >= off) ? sm[t - off] : 0;
        __syncthreads();
        sm[t] += u;
        __syncthreads();
    }
    if (t == 0) atomicExch(&g_bpub[b], sm[1023] + 1);
    if (t < 32) {
        int acc = 0;
        for (int j = t; j < b; j += 32) {
            int v;
            do { v = atomicAdd(&g_bpub[j], 0); } while (v == 0);
            acc += v - 1;
        }
        #pragma unroll
        for (int off = 16; off; off >>= 1) acc += __shfl_down_sync(~0u, acc, off);
        if (t == 0) s_off = acc;
    }
    __syncthreads();
    int off = s_off;
    if (i < n) {
        g_rowptr[i] = off + sm[t] - d;
        g_dinv[i] = rsqrtf((float)d + 1.0f);
    }
    if (b == nblk - 1 && t == 1023) g_rowptr[n] = off + sm[1023];
}

// -------- permute edges into CSR (atomic-free, rank-based) --------
__global__ void k_permute(const int* __restrict__ src, const int* __restrict__ dst, int E) {
    int stride = gridDim.x * blockDim.x;
    for (int e = blockIdx.x * blockDim.x + threadIdx.x; e < E; e += stride) {
        int d = dst[e];
        g_csr_src[g_rowptr[d] + g_erank[e]] = src[e];
    }
}

// ===================== fp16 HMMA GEMM (m16n8k16, 4m x 2n warp grid) =============
// out[n,128] = A[n,128] @ W[128,128]. A from fp32 (Af) or fp16 (Ah); out fp16.
__global__ void __launch_bounds__(256, 2)
k_gemm(const float* __restrict__ Af, const __half* __restrict__ Ah,
       const __half* __restrict__ Bt, __half* __restrict__ outh, int n) {
    extern __shared__ __half smh[];
    __half* As = smh;                // 128 x HST halves
    __half* Bs = smh + 128 * HST;    // 128 x HST halves  [n][k]

    int t = threadIdx.x;
    int r0 = blockIdx.x * 128;
    int rows = n - r0;
    if (rows > 128) rows = 128;

    for (int i = t; i < 128 * 32; i += 256) {
        int row = i >> 5, c4 = i & 31;
        *(uint2*)&Bs[row * HST + c4 * 4] = ((const uint2*)Bt)[i];
        uint2 av = make_uint2(0u, 0u);
        if (row < rows) {
            if (Af) {
                float4 v = ((const float4*)(Af + (size_t)r0 * D))[i];
                __half2 h01 = __floats2half2_rn(v.x, v.y);
                __half2 h23 = __floats2half2_rn(v.z, v.w);
                av.x = *(uint32_t*)&h01;
                av.y = *(uint32_t*)&h23;
            } else {
                av = ((const uint2*)(Ah + (size_t)r0 * D))[i];
            }
        }
        *(uint2*)&As[row * HST + c4 * 4] = av;
    }
    __syncthreads();

    int wid = t >> 5, lane = t & 31;
    int gid = lane >> 2, tig = lane & 3;
    int wm = wid >> 1, wn = wid & 1;

    float acc[2][8][4];
    #pragma unroll
    for (int s = 0; s < 2; s++)
        #pragma unroll
        for (int nt = 0; nt < 8; nt++)
            #pragma unroll
            for (int q = 0; q < 4; q++) acc[s][nt][q] = 0.0f;

    int ar0 = (wm * 32 + gid) * HST;          // subtile 0, row gid
    int ar1 = (wm * 32 + 8 + gid) * HST;      // subtile 0, row gid+8
    int ar2 = (wm * 32 + 16 + gid) * HST;     // subtile 1
    int ar3 = (wm * 32 + 24 + gid) * HST;

    #pragma unroll
    for (int k16 = 0; k16 < D; k16 += 16) {
        int c0 = k16 + 2 * tig;
        uint32_t a0[4], a1[4];
        a0[0] = *(const uint32_t*)&As[ar0 + c0];
        a0[1] = *(const uint32_t*)&As[ar1 + c0];
        a0[2] = *(const uint32_t*)&As[ar0 + c0 + 8];
        a0[3] = *(const uint32_t*)&As[ar1 + c0 + 8];
        a1[0] = *(const uint32_t*)&As[ar2 + c0];
        a1[1] = *(const uint32_t*)&As[ar3 + c0];
        a1[2] = *(const uint32_t*)&As[ar2 + c0 + 8];
        a1[3] = *(const uint32_t*)&As[ar3 + c0 + 8];

        #pragma unroll
        for (int nt = 0; nt < 8; nt++) {
            int br = (wn * 64 + nt * 8 + gid) * HST + c0;
            uint32_t b0 = *(const uint32_t*)&Bs[br];
            uint32_t b1 = *(const uint32_t*)&Bs[br + 8];
            mma16(acc[0][nt], a0, b0, b1);
            mma16(acc[1][nt], a1, b0, b1);
        }
    }

    #pragma unroll
    for (int s = 0; s < 2; s++) {
        int m0 = wm * 32 + s * 16 + gid;
        int m1 = m0 + 8;
        const int col = wn * 64 + 2 * tig;
        float* a01;
        #pragma unroll
        for (int nt = 0; nt < 8; nt++) {
            a01 = acc[s][nt];
            if (m0 < rows) {
                __half2 h = __floats2half2_rn(a01[0], a01[1]);
                *(__half2*)&outh[(size_t)(r0 + m0) * D + col + nt * 8] = h;
            }
            if (m1 < rows) {
                __half2 h = __floats2half2_rn(a01[2], a01[3]);
                *(__half2*)&outh[(size_t)(r0 + m1) * D + col + nt * 8] = h;
            }
        }
    }
}

// ===================== gather (all-fp16 activations) =====================
__device__ __forceinline__ void gcn_body(const __half* __restrict__ hh,
                                         const float* __restrict__ bias,
                                         int node, int lane, float4& r) {
    int beg = g_rowptr[node], end = g_rowptr[node + 1];
    float di = g_dinv[node];
    float4 acc = make_float4(0.f, 0.f, 0.f, 0.f);
    int e = beg;
    for (; e + 2 <= end; e += 2) {
        int s0 = g_csr_src[e], s1 = g_csr_src[e + 1];
        float c0 = g_dinv[s0] * di;
        float c1 = g_dinv[s1] * di;
        uint2 q0 = ((const uint2*)(hh + (size_t)s0 * D))[lane];
        uint2 q1 = ((const uint2*)(hh + (size_t)s1 * D))[lane];
        float2 a0 = __half22float2(*(__half2*)&q0.x);
        float2 a1 = __half22float2(*(__half2*)&q0.y);
        float2 b0 = __half22float2(*(__half2*)&q1.x);
        float2 b1 = __half22float2(*(__half2*)&q1.y);
        acc.x += c0 * a0.x + c1 * b0.x;
        acc.y += c0 * a0.y + c1 * b0.y;
        acc.z += c0 * a1.x + c1 * b1.x;
        acc.w += c0 * a1.y + c1 * b1.y;
    }
    if (e < end) {
        int s0 = g_csr_src[e];
        float c0 = g_dinv[s0] * di;
        uint2 q0 = ((const uint2*)(hh + (size_t)s0 * D))[lane];
        float2 a0 = __half22float2(*(__half2*)&q0.x);
        float2 a1 = __half22float2(*(__half2*)&q0.y);
        acc.x += c0 * a0.x; acc.y += c0 * a0.y;
        acc.z += c0 * a1.x; acc.w += c0 * a1.y;
    }
    uint2 qs = ((const uint2*)(hh + (size_t)node * D))[lane];
    float2 h0 = __half22float2(*(__half2*)&qs.x);
    float2 h1 = __half22float2(*(__half2*)&qs.y);
    float4 b = ((const float4*)bias)[lane];
    float d2 = di * di;
    r.x = lrelu(acc.x + h0.x * d2 + b.x);
    r.y = lrelu(acc.y + h0.y * d2 + b.y);
    r.z = lrelu(acc.z + h1.x * d2 + b.z);
    r.w = lrelu(acc.w + h1.y * d2 + b.w);
}

__global__ void k_gcn(const __half* __restrict__ hh, const float* __restrict__ bias,
                      __half* __restrict__ outh, int n) {
    int node = blockIdx.x * 8 + (threadIdx.x >> 5);
    if (node >= n) return;
    int lane = threadIdx.x & 31;
    float4 r;
    gcn_body(hh, bias, node, lane, r);
    __half2 o01 = __floats2half2_rn(r.x, r.y);
    __half2 o23 = __floats2half2_rn(r.z, r.w);
    uint2 o;
    o.x = *(uint32_t*)&o01;
    o.y = *(uint32_t*)&o23;
    ((uint2*)(outh + (size_t)node * D))[lane] = o;
}

__global__ void k_gcn_pool(const __half* __restrict__ hh, const float* __restrict__ bias,
                           const int* __restrict__ batch, int n) {
    int node = blockIdx.x * 8 + (threadIdx.x >> 5);
    if (node >= n) return;
    int lane = threadIdx.x & 31;
    float4 r;
    gcn_body(hh, bias, node, lane, r);
    int gid = batch[node];
    atomicAdd(((float4*)g_pool) + gid * 32 + lane, r);
}

// -------- head: out[g,c] = (pool[g]/cnt[g]) @ Wl + bl --------
__global__ void k_final(const float* __restrict__ Wl, const float* __restrict__ bl,
                        float* __restrict__ out) {
    int t = threadIdx.x;
    int g = t >> 4;
    int c = t & 15;
    float cnt = fmaxf(g_cnt[g], 1.0f);
    float s = 0.0f;
    #pragma unroll 8
    for (int f = 0; f < D; f++)
        s += g_pool[g * D + f] * Wl[f * CO + c];
    out[g * CO + c] = s / cnt + bl[c];
}

extern "C" void kernel_launch(void* const* d_in, const int* in_sizes, int n_in,
                              void* d_out, int out_size) {
    const float* x     = (const float*)d_in[0];
    const int*   ei    = (const int*)d_in[1];
    const int*   batch = (const int*)d_in[2];
    const float* W1    = (const float*)d_in[3];
    const float* b1    = (const float*)d_in[4];
    const float* W2    = (const float*)d_in[5];
    const float* b2    = (const float*)d_in[6];
    const float* Wl    = (const float*)d_in[7];
    const float* bl    = (const float*)d_in[8];

    int n = in_sizes[0] / D;
    int E = in_sizes[1] / 2;
    const int* src = ei;
    const int* dst = ei + E;

    void *pha, *phb, *pwh1, *pwh2;
    cudaGetSymbolAddress(&pha, g_ha);
    cudaGetSymbolAddress(&phb, g_hb);
    cudaGetSymbolAddress(&pwh1, g_WH1);
    cudaGetSymbolAddress(&pwh2, g_WH2);
    __half* ha = (__half*)pha;
    __half* hb = (__half*)phb;

    int smem = 2 * 128 * HST * (int)sizeof(__half);   // 69632 B
    cudaFuncSetAttribute(k_gemm, cudaFuncAttributeMaxDynamicSharedMemorySize, smem);

    int nblk = (n + 1023) / 1024;
    int nblocks8 = (n + 7) / 8;
    int gtiles = (n + 127) / 128;

    // CSR build
    k_init<<<512, 256>>>(W1, W2, n);
    k_hist<<<1024, 256>>>(dst, batch, E, n);
    k_scan<<<nblk, 1024>>>(n, nblk);
    k_permute<<<1024, 256>>>(src, dst, E);

    // Layer 1: ha = x@W1 (fp16) ; hb = gcn(ha)
    k_gemm<<<gtiles, 256, smem>>>(x, nullptr, (__half*)pwh1, ha, n);
    k_gcn<<<nblocks8, 256>>>(ha, b1, hb, n);

    // Layer 2: ha = hb@W2 ; pool += gcn(ha)
    k_gemm<<<gtiles, 256, smem>>>(nullptr, hb, (__half*)pwh2, ha, n);
    k_gcn_pool<<<nblocks8, 256>>>(ha, b2, batch, n);

    // Head
    k_final<<<1, 1024>>>(Wl, bl, (float*)d_out);
}

// round 12
// speedup vs baseline: 1.7035x; 1.0692x over previous
#include <cuda_runtime.h>
#include <cuda_fp16.h>
#include <cstdint>

#define D 128
#define NG 64
#define CO 16
#define MAXN 50176
#define MAXE 600064
#define NEG 0.1f
#define HST 136   // smem row stride in halves

// -------- scratch (device globals: allocation-free workaround) --------
__device__ __half g_ha[MAXN * D];     // GEMM outputs, pre-scaled by dinv[row]
__device__ __half g_hb[MAXN * D];     // gcn layer-1 output (unscaled)
__device__ __half g_WH1[D * D];       // W1^T fp16
__device__ __half g_WH2[D * D];       // W2^T fp16
__device__ float  g_dinv[MAXN];
__device__ int    g_degi[MAXN];
__device__ int    g_rowptr[MAXN + 1];
__device__ int    g_erank[MAXE];
__device__ int    g_csr_src[MAXE];
__device__ int    g_bpub[64];
__device__ float  g_pool[NG * D];
__device__ float  g_cnt[NG];

__device__ __forceinline__ float lrelu(float v) {
    return v >= 0.0f ? v : NEG * v;
}
__device__ __forceinline__ void mma16(float* c, const uint32_t* a, uint32_t b0, uint32_t b1) {
    asm volatile(
        "mma.sync.aligned.m16n8k16.row.col.f32.f16.f16.f32 "
        "{%0,%1,%2,%3}, {%4,%5,%6,%7}, {%8,%9}, {%0,%1,%2,%3};"
        : "+f"(c[0]), "+f"(c[1]), "+f"(c[2]), "+f"(c[3])
        : "r"(a[0]), "r"(a[1]), "r"(a[2]), "r"(a[3]), "r"(b0), "r"(b1));
}

// -------- init: zero degi/pool/cnt/bpub + fp16 W^T for both layers --------
__global__ void k_init(const float* __restrict__ W1, const float* __restrict__ W2, int n) {
    int stride = gridDim.x * blockDim.x;
    int i0 = blockIdx.x * blockDim.x + threadIdx.x;
    for (int i = i0; i < n; i += stride) g_degi[i] = 0;
    for (int i = i0; i < NG * D; i += stride) g_pool[i] = 0.0f;
    for (int i = i0; i < NG; i += stride) g_cnt[i] = 0.0f;
    for (int i = i0; i < 64; i += stride) g_bpub[i] = 0;
    for (int i = i0; i < D * D; i += stride) {
        int nn = i >> 7, k = i & 127;
        g_WH1[i] = __float2half_rn(W1[k * D + nn]);
        g_WH2[i] = __float2half_rn(W2[k * D + nn]);
    }
}

// -------- histogram over dst (record per-edge rank) + graph node counts --------
__global__ void k_hist(const int* __restrict__ dst, const int* __restrict__ batch,
                       int E, int n) {
    int stride = gridDim.x * blockDim.x;
    int i0 = blockIdx.x * blockDim.x + threadIdx.x;
    for (int e = i0; e < E; e += stride)
        g_erank[e] = atomicAdd(&g_degi[dst[e]], 1);
    for (int i = i0; i < n; i += stride)
        atomicAdd(&g_cnt[batch[i]], 1.0f);
}

// -------- single-kernel scan: decoupled lookback --------
__global__ void k_scan(int n, int nblk) {
    __shared__ int sm[1024];
    __shared__ int s_off;
    int t = threadIdx.x, b = blockIdx.x;
    int i = b * 1024 + t;
    int d = (i < n) ? g_degi[i] : 0;
    sm[t] = d;
    __syncthreads();
    #pragma unroll
    for (int off = 1; off < 1024; off <<= 1) {
        int u = (t >= off) ? sm[t - off] : 0;
        __syncthreads();
        sm[t] += u;
        __syncthreads();
    }
    if (t == 0) atomicExch(&g_bpub[b], sm[1023] + 1);
    if (t < 32) {
        int acc = 0;
        for (int j = t; j < b; j += 32) {
            int v;
            do { v = atomicAdd(&g_bpub[j], 0); } while (v == 0);
            acc += v - 1;
        }
        #pragma unroll
        for (int off = 16; off; off >>= 1) acc += __shfl_down_sync(~0u, acc, off);
        if (t == 0) s_off = acc;
    }
    __syncthreads();
    int off = s_off;
    if (i < n) {
        g_rowptr[i] = off + sm[t] - d;
        g_dinv[i] = rsqrtf((float)d + 1.0f);
    }
    if (b == nblk - 1 && t == 1023) g_rowptr[n] = off + sm[1023];
}

// -------- permute edges into CSR (atomic-free, rank-based) --------
__global__ void k_permute(const int* __restrict__ src, const int* __restrict__ dst, int E) {
    int stride = gridDim.x * blockDim.x;
    for (int e = blockIdx.x * blockDim.x + threadIdx.x; e < E; e += stride) {
        int d = dst[e];
        g_csr_src[g_rowptr[d] + g_erank[e]] = src[e];
    }
}

// ===================== fp16 HMMA GEMM (m16n8k16, 4m x 2n warp grid) =============
// outh[r,:] = dinv[r] * (A[r,:] @ W)  — pre-scaled for the dinv-folded gather.
__global__ void __launch_bounds__(256, 2)
k_gemm(const float* __restrict__ Af, const __half* __restrict__ Ah,
       const __half* __restrict__ Bt, __half* __restrict__ outh, int n) {
    extern __shared__ __half smh[];
    __half* As = smh;                // 128 x HST halves
    __half* Bs = smh + 128 * HST;    // 128 x HST halves  [n][k]

    int t = threadIdx.x;
    int r0 = blockIdx.x * 128;
    int rows = n - r0;
    if (rows > 128) rows = 128;

    for (int i = t; i < 128 * 32; i += 256) {
        int row = i >> 5, c4 = i & 31;
        *(uint2*)&Bs[row * HST + c4 * 4] = ((const uint2*)Bt)[i];
        uint2 av = make_uint2(0u, 0u);
        if (row < rows) {
            if (Af) {
                float4 v = ((const float4*)(Af + (size_t)r0 * D))[i];
                __half2 h01 = __floats2half2_rn(v.x, v.y);
                __half2 h23 = __floats2half2_rn(v.z, v.w);
                av.x = *(uint32_t*)&h01;
                av.y = *(uint32_t*)&h23;
            } else {
                av = ((const uint2*)(Ah + (size_t)r0 * D))[i];
            }
        }
        *(uint2*)&As[row * HST + c4 * 4] = av;
    }
    __syncthreads();

    int wid = t >> 5, lane = t & 31;
    int gid = lane >> 2, tig = lane & 3;
    int wm = wid >> 1, wn = wid & 1;

    float acc[2][8][4];
    #pragma unroll
    for (int s = 0; s < 2; s++)
        #pragma unroll
        for (int nt = 0; nt < 8; nt++)
            #pragma unroll
            for (int q = 0; q < 4; q++) acc[s][nt][q] = 0.0f;

    int ar0 = (wm * 32 + gid) * HST;
    int ar1 = (wm * 32 + 8 + gid) * HST;
    int ar2 = (wm * 32 + 16 + gid) * HST;
    int ar3 = (wm * 32 + 24 + gid) * HST;

    #pragma unroll
    for (int k16 = 0; k16 < D; k16 += 16) {
        int c0 = k16 + 2 * tig;
        uint32_t a0[4], a1[4];
        a0[0] = *(const uint32_t*)&As[ar0 + c0];
        a0[1] = *(const uint32_t*)&As[ar1 + c0];
        a0[2] = *(const uint32_t*)&As[ar0 + c0 + 8];
        a0[3] = *(const uint32_t*)&As[ar1 + c0 + 8];
        a1[0] = *(const uint32_t*)&As[ar2 + c0];
        a1[1] = *(const uint32_t*)&As[ar3 + c0];
        a1[2] = *(const uint32_t*)&As[ar2 + c0 + 8];
        a1[3] = *(const uint32_t*)&As[ar3 + c0 + 8];

        #pragma unroll
        for (int nt = 0; nt < 8; nt++) {
            int br = (wn * 64 + nt * 8 + gid) * HST + c0;
            uint32_t b0 = *(const uint32_t*)&Bs[br];
            uint32_t b1 = *(const uint32_t*)&Bs[br + 8];
            mma16(acc[0][nt], a0, b0, b1);
            mma16(acc[1][nt], a1, b0, b1);
        }
    }

    #pragma unroll
    for (int s = 0; s < 2; s++) {
        int m0 = wm * 32 + s * 16 + gid;
        int m1 = m0 + 8;
        const int col = wn * 64 + 2 * tig;
        float d0 = (m0 < rows) ? g_dinv[r0 + m0] : 0.f;
        float d1 = (m1 < rows) ? g_dinv[r0 + m1] : 0.f;
        #pragma unroll
        for (int nt = 0; nt < 8; nt++) {
            float* a01 = acc[s][nt];
            if (m0 < rows) {
                __half2 h = __floats2half2_rn(a01[0] * d0, a01[1] * d0);
                *(__half2*)&outh[(size_t)(r0 + m0) * D + col + nt * 8] = h;
            }
            if (m1 < rows) {
                __half2 h = __floats2half2_rn(a01[2] * d1, a01[3] * d1);
                *(__half2*)&outh[(size_t)(r0 + m1) * D + col + nt * 8] = h;
            }
        }
    }
}

// ===================== gather (dinv-folded: pure row sum, scale once) ===========
__device__ __forceinline__ void add_row(float4& acc, uint2 q) {
    float2 a0 = __half22float2(*(__half2*)&q.x);
    float2 a1 = __half22float2(*(__half2*)&q.y);
    acc.x += a0.x; acc.y += a0.y;
    acc.z += a1.x; acc.w += a1.y;
}

__device__ __forceinline__ void gcn_body(const __half* __restrict__ hh,
                                         const float* __restrict__ bias,
                                         int node, int lane, float4& r) {
    int beg = g_rowptr[node], end = g_rowptr[node + 1];
    float di = g_dinv[node];

    // self row (h' already scaled by dinv[node])
    float4 acc = make_float4(0.f, 0.f, 0.f, 0.f);
    add_row(acc, ((const uint2*)(hh + (size_t)node * D))[lane]);

    int e = beg;
    for (; e + 4 <= end; e += 4) {
        int s0 = g_csr_src[e];
        int s1 = g_csr_src[e + 1];
        int s2 = g_csr_src[e + 2];
        int s3 = g_csr_src[e + 3];
        uint2 q0 = ((const uint2*)(hh + (size_t)s0 * D))[lane];
        uint2 q1 = ((const uint2*)(hh + (size_t)s1 * D))[lane];
        uint2 q2 = ((const uint2*)(hh + (size_t)s2 * D))[lane];
        uint2 q3 = ((const uint2*)(hh + (size_t)s3 * D))[lane];
        add_row(acc, q0); add_row(acc, q1);
        add_row(acc, q2); add_row(acc, q3);
    }
    for (; e < end; e++) {
        int s0 = g_csr_src[e];
        add_row(acc, ((const uint2*)(hh + (size_t)s0 * D))[lane]);
    }

    float4 b = ((const float4*)bias)[lane];
    r.x = lrelu(di * acc.x + b.x);
    r.y = lrelu(di * acc.y + b.y);
    r.z = lrelu(di * acc.z + b.z);
    r.w = lrelu(di * acc.w + b.w);
}

__global__ void k_gcn(const __half* __restrict__ hh, const float* __restrict__ bias,
                      __half* __restrict__ outh, int n) {
    int node = blockIdx.x * 8 + (threadIdx.x >> 5);
    if (node >= n) return;
    int lane = threadIdx.x & 31;
    float4 r;
    gcn_body(hh, bias, node, lane, r);
    __half2 o01 = __floats2half2_rn(r.x, r.y);
    __half2 o23 = __floats2half2_rn(r.z, r.w);
    uint2 o;
    o.x = *(uint32_t*)&o01;
    o.y = *(uint32_t*)&o23;
    ((uint2*)(outh + (size_t)node * D))[lane] = o;
}

__global__ void k_gcn_pool(const __half* __restrict__ hh, const float* __restrict__ bias,
                           const int* __restrict__ batch, int n) {
    int node = blockIdx.x * 8 + (threadIdx.x >> 5);
    if (node >= n) return;
    int lane = threadIdx.x & 31;
    float4 r;
    gcn_body(hh, bias, node, lane, r);
    int gid = batch[node];
    atomicAdd(((float4*)g_pool) + gid * 32 + lane, r);
}

// -------- head: out[g,c] = (pool[g]/cnt[g]) @ Wl + bl --------
__global__ void k_final(const float* __restrict__ Wl, const float* __restrict__ bl,
                        float* __restrict__ out) {
    int t = threadIdx.x;
    int g = t >> 4;
    int c = t & 15;
    float cnt = fmaxf(g_cnt[g], 1.0f);
    float s = 0.0f;
    #pragma unroll 8
    for (int f = 0; f < D; f++)
        s += g_pool[g * D + f] * Wl[f * CO + c];
    out[g * CO + c] = s / cnt + bl[c];
}

extern "C" void kernel_launch(void* const* d_in, const int* in_sizes, int n_in,
                              void* d_out, int out_size) {
    const float* x     = (const float*)d_in[0];
    const int*   ei    = (const int*)d_in[1];
    const int*   batch = (const int*)d_in[2];
    const float* W1    = (const float*)d_in[3];
    const float* b1    = (const float*)d_in[4];
    const float* W2    = (const float*)d_in[5];
    const float* b2    = (const float*)d_in[6];
    const float* Wl    = (const float*)d_in[7];
    const float* bl    = (const float*)d_in[8];

    int n = in_sizes[0] / D;
    int E = in_sizes[1] / 2;
    const int* src = ei;
    const int* dst = ei + E;

    void *pha, *phb, *pwh1, *pwh2;
    cudaGetSymbolAddress(&pha, g_ha);
    cudaGetSymbolAddress(&phb, g_hb);
    cudaGetSymbolAddress(&pwh1, g_WH1);
    cudaGetSymbolAddress(&pwh2, g_WH2);
    __half* ha = (__half*)pha;
    __half* hb = (__half*)phb;

    int smem = 2 * 128 * HST * (int)sizeof(__half);   // 69632 B
    cudaFuncSetAttribute(k_gemm, cudaFuncAttributeMaxDynamicSharedMemorySize, smem);

    int nblk = (n + 1023) / 1024;
    int nblocks8 = (n + 7) / 8;
    int gtiles = (n + 127) / 128;

    // CSR build
    k_init<<<512, 256>>>(W1, W2, n);
    k_hist<<<1024, 256>>>(dst, batch, E, n);
    k_scan<<<nblk, 1024>>>(n, nblk);
    k_permute<<<1024, 256>>>(src, dst, E);

    // Layer 1: ha = dinv*(x@W1) ; hb = gcn(ha)
    k_gemm<<<gtiles, 256, smem>>>(x, nullptr, (__half*)pwh1, ha, n);
    k_gcn<<<nblocks8, 256>>>(ha, b1, hb, n);

    // Layer 2: ha = dinv*(hb@W2) ; pool += gcn(ha)
    k_gemm<<<gtiles, 256, smem>>>(nullptr, hb, (__half*)pwh2, ha, n);
    k_gcn_pool<<<nblocks8, 256>>>(ha, b2, batch, n);

    // Head
    k_final<<<1, 1024>>>(Wl, bl, (float*)d_out);
}